// round 12
// baseline (speedup 1.0000x reference)
#include <cuda_runtime.h>
#include <math.h>

#define B_  64
#define T_  2048
#define D_  128
#define U_  128
#define G3  384          // 3*U
#define BT  131072       // B*T

typedef unsigned long long ull;

// ---------------- f32x2 helpers (proven R9/R11) ----------------
__device__ __forceinline__ ull pack2(float lo, float hi) {
    ull r; asm("mov.b64 %0, {%1,%2};" : "=l"(r) : "f"(lo), "f"(hi)); return r;
}
__device__ __forceinline__ float hsum2(ull a, ull b) {
    float alo, ahi, blo, bhi;
    asm("mov.b64 {%0,%1}, %2;" : "=f"(alo), "=f"(ahi) : "l"(a));
    asm("mov.b64 {%0,%1}, %2;" : "=f"(blo), "=f"(bhi) : "l"(b));
    return (alo + blo) + (ahi + bhi);
}
__device__ __forceinline__ ull ffma2(ull a, ull b, ull c) {
    ull d; asm("fma.rn.f32x2 %0, %1, %2, %3;" : "=l"(d) : "l"(a), "l"(b), "l"(c)); return d;
}

// ---------------- scratch (static device buffers; no allocation) ----------------
__device__ float g_W2[D_ * G3];              // sub_kernel_x transposed to (d, n*128+i)
__device__ float g_XK[(size_t)BT * G3];      // x@kernel + bias        (b,t,j)
__device__ float g_XS[(size_t)BT * G3];      // x@sub_kernel_x         (b,t,j)
__device__ float g_SO[(size_t)BT * G3];      // sub_o per step, (t, n, b, o) = FLAT rows
__device__ float g_PO[(size_t)BT * U_];      // sigmoid(flat@agg_w+agg_b), (t, b, u)

// ---------------- W2 transpose: W2[d][n*128+i] = skx[n][d][i] ----------------
__global__ void build_w2_kernel(const float* __restrict__ skx) {
    int idx = blockIdx.x * 256 + threadIdx.x;   // over 3*128*128 = 49152
    if (idx < 3 * 128 * 128) {
        int n = idx / 16384;
        int rem = idx - n * 16384;
        int d = rem >> 7;
        int i = rem & 127;
        g_W2[d * G3 + n * 128 + i] = skx[idx];
    }
}

// ---------------- fast fp32 GEMM: C[M,N] = act(A[M,K] @ W[K,N] + bias) ----------------
__global__ __launch_bounds__(256, 2) void gemm128_kernel(
    const float* __restrict__ A, const float* __restrict__ W,
    const float* __restrict__ bias, float* __restrict__ C,
    int M, int K, int N, int act)
{
    __shared__ float As[2][8][132];   // [buf][k][m], padded
    __shared__ float Bs[2][8][128];   // [buf][k][n]

    const int tid = threadIdx.x;
    const int m0 = blockIdx.x * 128;
    const int n0 = blockIdx.y * 128;

    const int la_m = tid >> 1;
    const int la_k = (tid & 1) * 4;
    const int lb_k = tid >> 5;
    const int lb_n = (tid & 31) * 4;

    const int tx = tid & 15;
    const int ty = tid >> 4;

    float acc[8][8];
#pragma unroll
    for (int r = 0; r < 8; r++)
#pragma unroll
        for (int c = 0; c < 8; c++) acc[r][c] = 0.f;

    const float* aptr = A + (size_t)(m0 + la_m) * K + la_k;
    const float* bptr = W + (size_t)lb_k * N + n0 + lb_n;

    {
        float4 ga = *reinterpret_cast<const float4*>(aptr);
        float4 gb = *reinterpret_cast<const float4*>(bptr);
        As[0][la_k + 0][la_m] = ga.x;
        As[0][la_k + 1][la_m] = ga.y;
        As[0][la_k + 2][la_m] = ga.z;
        As[0][la_k + 3][la_m] = ga.w;
        *reinterpret_cast<float4*>(&Bs[0][lb_k][lb_n]) = gb;
    }
    __syncthreads();

    const int nkt = K >> 3;
    float4 ga, gb;
#pragma unroll 1
    for (int kt = 0; kt < nkt; kt++) {
        const int cur = kt & 1;
        const int nxt = cur ^ 1;
        if (kt + 1 < nkt) {
            ga = *reinterpret_cast<const float4*>(aptr + (size_t)(kt + 1) * 8);
            gb = *reinterpret_cast<const float4*>(bptr + (size_t)(kt + 1) * 8 * N);
        }
#pragma unroll
        for (int kk = 0; kk < 8; kk++) {
            float4 a0 = *reinterpret_cast<const float4*>(&As[cur][kk][ty * 4]);
            float4 a1 = *reinterpret_cast<const float4*>(&As[cur][kk][64 + ty * 4]);
            float4 b0 = *reinterpret_cast<const float4*>(&Bs[cur][kk][tx * 4]);
            float4 b1 = *reinterpret_cast<const float4*>(&Bs[cur][kk][64 + tx * 4]);
            float am[8] = {a0.x, a0.y, a0.z, a0.w, a1.x, a1.y, a1.z, a1.w};
            float bn[8] = {b0.x, b0.y, b0.z, b0.w, b1.x, b1.y, b1.z, b1.w};
#pragma unroll
            for (int r = 0; r < 8; r++)
#pragma unroll
                for (int c = 0; c < 8; c++)
                    acc[r][c] += am[r] * bn[c];
        }
        if (kt + 1 < nkt) {
            __syncthreads();
            As[nxt][la_k + 0][la_m] = ga.x;
            As[nxt][la_k + 1][la_m] = ga.y;
            As[nxt][la_k + 2][la_m] = ga.z;
            As[nxt][la_k + 3][la_m] = ga.w;
            *reinterpret_cast<float4*>(&Bs[nxt][lb_k][lb_n]) = gb;
            __syncthreads();
        }
    }

#pragma unroll
    for (int r = 0; r < 8; r++) {
        const int mm = (r < 4) ? (ty * 4 + r) : (64 + ty * 4 + r - 4);
        float out[8];
#pragma unroll
        for (int c = 0; c < 8; c++) {
            const int nn = (c < 4) ? (tx * 4 + c) : (64 + tx * 4 + c - 4);
            float v = acc[r][c];
            if (bias) v += bias[n0 + nn];
            if (act == 1) v = 1.f / (1.f + __expf(-v));
            out[c] = v;
        }
        float* crow = C + (size_t)(m0 + mm) * N + n0;
        *reinterpret_cast<float4*>(&crow[tx * 4])      = make_float4(out[0], out[1], out[2], out[3]);
        *reinterpret_cast<float4*>(&crow[64 + tx * 4]) = make_float4(out[4], out[5], out[6], out[7]);
    }
}

// ---------------- Phase A: s-recurrence, one CTA per (n, batch-pair) -----------------
// 96 CTAs x 256 threads. thread (i, half): half-split reductions, ALL weights in regs,
// all smem loads are broadcasts. aP/eP hold half-partials; 3 barriers/step.
__global__ __launch_bounds__(256, 1) void phaseA_kernel(
    const float* __restrict__ subh,   // (3,128,128) [n][o][i]
    const float* __restrict__ densew, // (3,128,128) [n][i][o]
    const float* __restrict__ denseb, // (3,128)
    const float* __restrict__ tkan)   // (3,256)
{
    __shared__ __align__(16) float s_sm[2][2][128];   // [pp][batch][i]
    __shared__ __align__(16) float aP[2][2][128];     // [half][batch][i] stage-1 partials
    __shared__ __align__(16) float eP[2][2][128];     // [half][batch][i] stage-2 partials

    const int bid  = blockIdx.x;
    const int n    = bid >> 5;          // 0..2
    const int b0   = (bid & 31) * 2;    // 0,2,..,62
    const int tid  = threadIdx.x;
    const int i    = tid & 127;
    const int half = tid >> 7;          // 0/1: handles o (stage1) / i' (stage2) in [64*half, 64*half+63]
    const int obase = half * 64;

    // weights in registers, packed f32x2 over the reduced dimension
    ull w2[32], d2[32];
#pragma unroll
    for (int q = 0; q < 32; q++) {
        // stage1: w2[q] <-> o = obase+2q, obase+2q+1 ; subh[n][o][i]
        float wl = __ldg(&subh[(n * 128 + obase + 2 * q) * 128 + i]);
        float wh = __ldg(&subh[(n * 128 + obase + 2 * q + 1) * 128 + i]);
        w2[q] = pack2(wl, wh);
        // stage2: d2[q] <-> i' = obase+2q, +1 ; densew[n][i'][o=i]
        float dl = __ldg(&densew[n * 16384 + (obase + 2 * q) * 128 + i]);
        float dh = __ldg(&densew[n * 16384 + (obase + 2 * q + 1) * 128 + i]);
        d2[q] = pack2(dl, dh);
    }

    const float rh = tkan[n * 256 + i];
    const float rx = tkan[n * 256 + 128 + i];
    const float db = denseb[n * 128 + i];

    ((float*)s_sm)[tid] = 0.f;          // zero pp buffer 0 (256 floats)
    __syncthreads();

    const float* xs0p = g_XS + (size_t)b0 * T_ * G3 + n * 128 + i;
    const float* xs1p = xs0p + (size_t)T_ * G3;
    float*       so_p = g_SO + (size_t)n * 8192 + (size_t)b0 * 128 + i;

    float xs0 = 0.f, xs1 = 0.f;
    if (half == 0) { xs0 = __ldg(xs0p); xs1 = __ldg(xs1p); }
    xs0p += G3; xs1p += G3;

#pragma unroll 1
    for (int t = 0; t < T_; t++) {
        float nx0 = 0.f, nx1 = 0.f;
        if (half == 0 && t + 1 < T_) { nx0 = __ldg(xs0p); nx1 = __ldg(xs1p); }

        const float* scur = &s_sm[t & 1][0][0];
        float*       snxt = &s_sm[(t & 1) ^ 1][0][0];

        // ---- stage 1: partial agg over o in [obase, obase+64) (s reads broadcast) ----
        const ulonglong2* s0 = reinterpret_cast<const ulonglong2*>(scur + obase);
        const ulonglong2* s1 = reinterpret_cast<const ulonglong2*>(scur + 128 + obase);
        ull a00 = 0, a01 = 0, a10 = 0, a11 = 0;
#pragma unroll
        for (int q = 0; q < 16; q++) {
            ulonglong2 sa = s0[q];                  // s[b0][obase+4q .. +3]
            a00 = ffma2(sa.x, w2[2 * q],     a00);
            a01 = ffma2(sa.y, w2[2 * q + 1], a01);
            ulonglong2 sb = s1[q];                  // s[b1]
            a10 = ffma2(sb.x, w2[2 * q],     a10);
            a11 = ffma2(sb.y, w2[2 * q + 1], a11);
        }
        float p0 = hsum2(a00, a01);
        float p1 = hsum2(a10, a11);
        if (half == 0) { p0 += xs0; p1 += xs1; }    // fold xs into half-0 partial
        aP[half][0][i] = p0;
        aP[half][1][i] = p1;
        __syncthreads();

        // ---- stage 2: partial dense over i' in [obase, obase+64) (a reads broadcast) ----
        const ulonglong2* A0b0 = reinterpret_cast<const ulonglong2*>(&aP[0][0][0] + obase);
        const ulonglong2* A1b0 = reinterpret_cast<const ulonglong2*>(&aP[1][0][0] + obase);
        const ulonglong2* A0b1 = reinterpret_cast<const ulonglong2*>(&aP[0][1][0] + obase);
        const ulonglong2* A1b1 = reinterpret_cast<const ulonglong2*>(&aP[1][1][0] + obase);
        ull e00 = 0, e01 = 0, e10 = 0, e11 = 0;
        ull f00 = 0, f01 = 0, f10 = 0, f11 = 0;
#pragma unroll
        for (int q = 0; q < 16; q++) {
            ulonglong2 u0 = A0b0[q];
            ulonglong2 v0 = A1b0[q];
            e00 = ffma2(u0.x, d2[2 * q],     e00);
            e01 = ffma2(u0.y, d2[2 * q + 1], e01);
            f00 = ffma2(v0.x, d2[2 * q],     f00);
            f01 = ffma2(v0.y, d2[2 * q + 1], f01);
            ulonglong2 u1 = A0b1[q];
            ulonglong2 v1 = A1b1[q];
            e10 = ffma2(u1.x, d2[2 * q],     e10);
            e11 = ffma2(u1.y, d2[2 * q + 1], e11);
            f10 = ffma2(v1.x, d2[2 * q],     f10);
            f11 = ffma2(v1.y, d2[2 * q + 1], f11);
        }
        eP[half][0][i] = hsum2(e00, e01) + hsum2(f00, f01);
        eP[half][1][i] = hsum2(e10, e11) + hsum2(f10, f11);
        __syncthreads();

        // ---- finalize: both halves compute so (cheap), split the stores ----
        float so0 = fmaxf(db + eP[0][0][i] + eP[1][0][i], 0.f);
        float so1 = fmaxf(db + eP[0][1][i] + eP[1][1][i], 0.f);
        if (half == 0) {
            snxt[i]       = rh * so0 + scur[i] * rx;
            snxt[128 + i] = rh * so1 + scur[128 + i] * rx;
        } else {
            so_p[0]   = so0;
            so_p[128] = so1;
        }
        __syncthreads();

        xs0 = nx0; xs1 = nx1;
        xs0p += G3; xs1p += G3;
        so_p += 24576;   // 3*64*128 per step
    }
}

// ---------------- Phase C: per-batch h/c recurrence (64 CTAs x 384 threads) ----------------
// f32x2 packed FMAs, full 128-wide k range (R9/R11-proven).
__global__ __launch_bounds__(384, 1) void phaseC_kernel(
    const float* __restrict__ R,      // (128, 384)
    float* __restrict__ out)          // (B, T, U)
{
    __shared__ __align__(16) float h_sm[256];   // ping-pong [2][128]
    __shared__ float g_sm[384];

    const int b = blockIdx.x;
    const int j = threadIdx.x;

    ull wc[64];
#pragma unroll
    for (int q = 0; q < 64; q++) {
        float lo = __ldg(&R[(2 * q) * G3 + j]);
        float hi = __ldg(&R[(2 * q + 1) * G3 + j]);
        wc[q] = pack2(lo, hi);
    }

    float c = 0.f;
    if (j < 128) h_sm[j] = 0.f;
    __syncthreads();

    const float* xk_ptr  = g_XK + (size_t)b * T_ * G3 + j;
    const float* po_ptr  = g_PO + (size_t)b * U_ + j;     // valid only for j<128
    float*       out_ptr = out  + (size_t)b * T_ * U_ + j;

    float z0 = __ldg(xk_ptr);
    float og0 = (j < 128) ? __ldg(po_ptr) : 0.f;
    xk_ptr += G3; po_ptr += 8192;

#pragma unroll 1
    for (int t = 0; t < T_; t++) {
        float nz = 0.f, nog = 0.f;
        if (t + 1 < T_) {
            nz = __ldg(xk_ptr);
            if (j < 128) nog = __ldg(po_ptr);
        }

        const ulonglong2* h22 = reinterpret_cast<const ulonglong2*>(h_sm + (t & 1) * 128);
        ull acc0 = 0, acc1 = 0;
#pragma unroll
        for (int q = 0; q < 32; q++) {
            ulonglong2 hv = h22[q];
            acc0 = ffma2(hv.x, wc[2 * q],     acc0);
            acc1 = ffma2(hv.y, wc[2 * q + 1], acc1);
        }
        float z = z0 + hsum2(acc0, acc1);
        g_sm[j] = 1.f / (1.f + __expf(-z));
        __syncthreads();

        if (j < 128) {
            float ig = g_sm[j];
            float fg = g_sm[128 + j];
            float cg = g_sm[256 + j];
            c = fg * c + ig * tanhf(cg);
            float h = og0 * tanhf(c);
            *out_ptr = h;
            h_sm[((t & 1) ^ 1) * 128 + j] = h;
        }
        __syncthreads();

        z0 = nz; og0 = nog;
        xk_ptr += G3; po_ptr += 8192; out_ptr += U_;
    }
}

// ---------------- launch ----------------
extern "C" void kernel_launch(void* const* d_in, const int* in_sizes, int n_in,
                              void* d_out, int out_size)
{
    (void)in_sizes; (void)n_in; (void)out_size;
    const float* x      = (const float*)d_in[0];   // (64,2048,128)
    const float* kern   = (const float*)d_in[1];   // (128,384)
    const float* reck   = (const float*)d_in[2];   // (128,384)
    const float* bias   = (const float*)d_in[3];   // (384)
    const float* skx    = (const float*)d_in[4];   // (3,128,128)
    const float* skh    = (const float*)d_in[5];   // (3,128,128)
    const float* tkan   = (const float*)d_in[6];   // (3,256)
    const float* dw     = (const float*)d_in[7];   // (3,128,128)
    const float* dbv    = (const float*)d_in[8];   // (3,128)
    const float* aggw   = (const float*)d_in[9];   // (384,128)
    const float* aggb   = (const float*)d_in[10];  // (128)
    float* out = (float*)d_out;

    void *pW2, *pXK, *pXS, *pSO, *pPO;
    cudaGetSymbolAddress(&pW2, g_W2);
    cudaGetSymbolAddress(&pXK, g_XK);
    cudaGetSymbolAddress(&pXS, g_XS);
    cudaGetSymbolAddress(&pSO, g_SO);
    cudaGetSymbolAddress(&pPO, g_PO);

    // side stream + events for overlapping the XK GEMM with the main chain
    static cudaStream_t s2 = nullptr;
    static cudaEvent_t evF = nullptr, evX = nullptr;
    if (s2 == nullptr) {
        cudaStreamCreateWithFlags(&s2, cudaStreamNonBlocking);
        cudaEventCreateWithFlags(&evF, cudaEventDisableTiming);
        cudaEventCreateWithFlags(&evX, cudaEventDisableTiming);
    }

    // fork: XK = x@kernel + bias on side stream (independent of everything else)
    cudaEventRecord(evF, 0);
    cudaStreamWaitEvent(s2, evF, 0);
    {
        dim3 grid(BT / 128, G3 / 128);
        gemm128_kernel<<<grid, 256, 0, s2>>>(x, kern, bias, (float*)pXK, BT, D_, G3, 0);
    }
    cudaEventRecord(evX, s2);

    // main stream: W2 transpose, XS GEMM, phaseA, PO GEMM
    build_w2_kernel<<<192, 256>>>(skx);
    {
        dim3 grid(BT / 128, G3 / 128);
        gemm128_kernel<<<grid, 256>>>(x, (const float*)pW2, nullptr, (float*)pXS, BT, D_, G3, 0);
    }

    phaseA_kernel<<<96, 256>>>(skh, dw, dbv, tkan);

    {
        dim3 grid(BT / 128, U_ / 128);
        gemm128_kernel<<<grid, 256>>>((const float*)pSO, aggw, aggb, (float*)pPO, BT, G3, U_, 1);
    }

    // join: phaseC needs XK (side stream) + PO
    cudaStreamWaitEvent(0, evX, 0);
    phaseC_kernel<<<B_, G3>>>(reck, out);
}

// round 13
// speedup vs baseline: 1.0801x; 1.0801x over previous
#include <cuda_runtime.h>
#include <math.h>

#define B_  64
#define T_  2048
#define D_  128
#define U_  128
#define G3  384          // 3*U
#define BT  131072       // B*T
#define CH  256          // chunk length (steps)
#define NCH (T_ / CH)    // 8 chunks

typedef unsigned long long ull;

// ---------------- f32x2 helpers (proven R9/R11) ----------------
__device__ __forceinline__ ull pack2(float lo, float hi) {
    ull r; asm("mov.b64 %0, {%1,%2};" : "=l"(r) : "f"(lo), "f"(hi)); return r;
}
__device__ __forceinline__ float hsum2(ull a, ull b) {
    float alo, ahi, blo, bhi;
    asm("mov.b64 {%0,%1}, %2;" : "=f"(alo), "=f"(ahi) : "l"(a));
    asm("mov.b64 {%0,%1}, %2;" : "=f"(blo), "=f"(bhi) : "l"(b));
    return (alo + blo) + (ahi + bhi);
}
__device__ __forceinline__ ull ffma2(ull a, ull b, ull c) {
    ull d; asm("fma.rn.f32x2 %0, %1, %2, %3;" : "=l"(d) : "l"(a), "l"(b), "l"(c)); return d;
}

// ---------------- scratch (static device buffers; no allocation) ----------------
__device__ float g_W2[D_ * G3];              // sub_kernel_x transposed to (d, n*128+i)
__device__ float g_DT[3 * 128 * 128];        // dense_w transposed: [n][o*128 + i']
__device__ float g_XK[(size_t)BT * G3];      // x@kernel + bias        (b,t,j)
__device__ float g_XS[(size_t)BT * G3];      // x@sub_kernel_x         (b,t,j)
__device__ float g_SO[(size_t)BT * G3];      // sub_o per step, (t, n, b, o) = FLAT rows
__device__ float g_PO[(size_t)BT * U_];      // sigmoid(flat@agg_w+agg_b), (t, b, u)
__device__ float g_SS[96 * 256];             // phaseA chunk-boundary s state per CTA
__device__ float g_HC[64 * 256];             // phaseC chunk-boundary h (0..127) / c (128..255)

// ---------------- W2 transpose: W2[d][n*128+i] = skx[n][d][i] ----------------
__global__ void build_w2_kernel(const float* __restrict__ skx) {
    int idx = blockIdx.x * 256 + threadIdx.x;   // over 3*128*128 = 49152
    if (idx < 3 * 128 * 128) {
        int n = idx / 16384;
        int rem = idx - n * 16384;
        int d = rem >> 7;
        int i = rem & 127;
        g_W2[d * G3 + n * 128 + i] = skx[idx];
    }
}

// ---------------- DT transpose: DT[n][o*128+ii] = densew[n][ii*128+o] ----------------
__global__ void build_dt_kernel(const float* __restrict__ densew) {
    int idx = blockIdx.x * 256 + threadIdx.x;   // over 3*128*128
    if (idx < 3 * 128 * 128) {
        int n  = idx >> 14;
        int rem = idx & 16383;
        int o  = rem >> 7;
        int ii = rem & 127;
        g_DT[n * 16384 + o * 128 + ii] = densew[n * 16384 + ii * 128 + o];
    }
}

// ---------------- fast fp32 GEMM: C[M,N] = act(A[M,K] @ W[K,N] + bias) ----------------
__global__ __launch_bounds__(256, 2) void gemm128_kernel(
    const float* __restrict__ A, const float* __restrict__ W,
    const float* __restrict__ bias, float* __restrict__ C,
    int M, int K, int N, int act)
{
    __shared__ float As[2][8][132];   // [buf][k][m], padded
    __shared__ float Bs[2][8][128];   // [buf][k][n]

    const int tid = threadIdx.x;
    const int m0 = blockIdx.x * 128;
    const int n0 = blockIdx.y * 128;

    const int la_m = tid >> 1;
    const int la_k = (tid & 1) * 4;
    const int lb_k = tid >> 5;
    const int lb_n = (tid & 31) * 4;

    const int tx = tid & 15;
    const int ty = tid >> 4;

    float acc[8][8];
#pragma unroll
    for (int r = 0; r < 8; r++)
#pragma unroll
        for (int c = 0; c < 8; c++) acc[r][c] = 0.f;

    const float* aptr = A + (size_t)(m0 + la_m) * K + la_k;
    const float* bptr = W + (size_t)lb_k * N + n0 + lb_n;

    {
        float4 ga = *reinterpret_cast<const float4*>(aptr);
        float4 gb = *reinterpret_cast<const float4*>(bptr);
        As[0][la_k + 0][la_m] = ga.x;
        As[0][la_k + 1][la_m] = ga.y;
        As[0][la_k + 2][la_m] = ga.z;
        As[0][la_k + 3][la_m] = ga.w;
        *reinterpret_cast<float4*>(&Bs[0][lb_k][lb_n]) = gb;
    }
    __syncthreads();

    const int nkt = K >> 3;
    float4 ga, gb;
#pragma unroll 1
    for (int kt = 0; kt < nkt; kt++) {
        const int cur = kt & 1;
        const int nxt = cur ^ 1;
        if (kt + 1 < nkt) {
            ga = *reinterpret_cast<const float4*>(aptr + (size_t)(kt + 1) * 8);
            gb = *reinterpret_cast<const float4*>(bptr + (size_t)(kt + 1) * 8 * N);
        }
#pragma unroll
        for (int kk = 0; kk < 8; kk++) {
            float4 a0 = *reinterpret_cast<const float4*>(&As[cur][kk][ty * 4]);
            float4 a1 = *reinterpret_cast<const float4*>(&As[cur][kk][64 + ty * 4]);
            float4 b0 = *reinterpret_cast<const float4*>(&Bs[cur][kk][tx * 4]);
            float4 b1 = *reinterpret_cast<const float4*>(&Bs[cur][kk][64 + tx * 4]);
            float am[8] = {a0.x, a0.y, a0.z, a0.w, a1.x, a1.y, a1.z, a1.w};
            float bn[8] = {b0.x, b0.y, b0.z, b0.w, b1.x, b1.y, b1.z, b1.w};
#pragma unroll
            for (int r = 0; r < 8; r++)
#pragma unroll
                for (int c = 0; c < 8; c++)
                    acc[r][c] += am[r] * bn[c];
        }
        if (kt + 1 < nkt) {
            __syncthreads();
            As[nxt][la_k + 0][la_m] = ga.x;
            As[nxt][la_k + 1][la_m] = ga.y;
            As[nxt][la_k + 2][la_m] = ga.z;
            As[nxt][la_k + 3][la_m] = ga.w;
            *reinterpret_cast<float4*>(&Bs[nxt][lb_k][lb_n]) = gb;
            __syncthreads();
        }
    }

#pragma unroll
    for (int r = 0; r < 8; r++) {
        const int mm = (r < 4) ? (ty * 4 + r) : (64 + ty * 4 + r - 4);
        float out[8];
#pragma unroll
        for (int c = 0; c < 8; c++) {
            const int nn = (c < 4) ? (tx * 4 + c) : (64 + tx * 4 + c - 4);
            float v = acc[r][c];
            if (bias) v += bias[n0 + nn];
            if (act == 1) v = 1.f / (1.f + __expf(-v));
            out[c] = v;
        }
        float* crow = C + (size_t)(m0 + mm) * N + n0;
        *reinterpret_cast<float4*>(&crow[tx * 4])      = make_float4(out[0], out[1], out[2], out[3]);
        *reinterpret_cast<float4*>(&crow[64 + tx * 4]) = make_float4(out[4], out[5], out[6], out[7]);
    }
}

// ---------------- Phase A: s-recurrence, chunked; one CTA per (n, batch-pair) --------
// 96 CTAs x 128 threads (R11-proven math). Steps [t0, t0+CH); s state via g_SS.
#define DT_ROW   132
#define DT_N2    (128 * DT_ROW)               // 16896 floats (one n)
#define SA2_OFF  DT_N2                        // s ping-pong: [2][2][128] = 512
#define AA2_OFF  (SA2_OFF + 512)              // agg: [2][128] = 256
#define SMEM_A2_FLOATS (AA2_OFF + 256)        // 17664 floats = 70,656 B
__global__ __launch_bounds__(128, 1) void phaseA_kernel(
    const float* __restrict__ subh,   // (3,128,128) [n][o][i]
    const float* __restrict__ denseb, // (3,128)
    const float* __restrict__ tkan,   // (3,256)
    int t0)
{
    extern __shared__ float sm[];
    float* dsm  = sm;                 // dT[o*132 + i']
    float* s_sm = sm + SA2_OFF;       // [pp][batch][128]
    float* a_sm = sm + AA2_OFF;       // [batch][128]

    const int bid = blockIdx.x;
    const int n  = bid >> 5;          // 0..2
    const int b0 = (bid & 31) * 2;    // 0,2,..,62
    const int i  = threadIdx.x;       // 0..127

    // copy this n's pre-transposed dense_w into padded smem (coalesced)
    for (int idx = i; idx < 128 * 128; idx += 128) {
        int oo = idx >> 7;
        int ii = idx & 127;
        dsm[oo * DT_ROW + ii] = g_DT[n * 16384 + idx];
    }

    // packed sub_h column: w2[q] = (subh[n][2q][i], subh[n][2q+1][i])
    ull w2[64];
#pragma unroll
    for (int q = 0; q < 64; q++) {
        float lo = __ldg(&subh[(n * 128 + 2 * q) * 128 + i]);
        float hi = __ldg(&subh[(n * 128 + 2 * q + 1) * 128 + i]);
        w2[q] = pack2(lo, hi);
    }

    const float rh = tkan[n * 256 + i];
    const float rx = tkan[n * 256 + 128 + i];
    const float db = denseb[n * 128 + i];

    // load / init s state into pp buffer 0
    if (t0 == 0) {
        s_sm[i] = 0.f;  s_sm[128 + i] = 0.f;
    } else {
        s_sm[i]       = g_SS[bid * 256 + i];
        s_sm[128 + i] = g_SS[bid * 256 + 128 + i];
    }
    __syncthreads();

    const float* xs0p = g_XS + (size_t)b0 * T_ * G3 + (size_t)t0 * G3 + n * 128 + i;
    const float* xs1p = xs0p + (size_t)T_ * G3;
    float*       so_p = g_SO + (size_t)t0 * 24576 + (size_t)n * 8192 + (size_t)b0 * 128 + i;
    const ulonglong2* d22 = reinterpret_cast<const ulonglong2*>(dsm + i * DT_ROW);

    float xs0 = __ldg(xs0p), xs1 = __ldg(xs1p);
    xs0p += G3; xs1p += G3;

#pragma unroll 1
    for (int t = 0; t < CH; t++) {
        float nx0 = 0.f, nx1 = 0.f;
        if (t0 + t + 1 < T_) { nx0 = __ldg(xs0p); nx1 = __ldg(xs1p); }

        const float* scur = s_sm + (t & 1) * 256;
        float*       snxt = s_sm + ((t & 1) ^ 1) * 256;

        // ---- stage 1: agg_in for both batches (sum over o) ----
        const ulonglong2* s22_0 = reinterpret_cast<const ulonglong2*>(scur);
        const ulonglong2* s22_1 = reinterpret_cast<const ulonglong2*>(scur + 128);
        ull a00 = 0, a01 = 0, a10 = 0, a11 = 0;
#pragma unroll
        for (int q = 0; q < 32; q++) {
            ulonglong2 sa = s22_0[q];
            a00 = ffma2(sa.x, w2[2 * q],     a00);
            a01 = ffma2(sa.y, w2[2 * q + 1], a01);
            ulonglong2 sb = s22_1[q];
            a10 = ffma2(sb.x, w2[2 * q],     a10);
            a11 = ffma2(sb.y, w2[2 * q + 1], a11);
        }
        a_sm[i]       = xs0 + hsum2(a00, a01);
        a_sm[128 + i] = xs1 + hsum2(a10, a11);
        __syncthreads();

        // ---- stage 2: dense + relu + s update (dT read once, used for both) ----
        const ulonglong2* a22_0 = reinterpret_cast<const ulonglong2*>(a_sm);
        const ulonglong2* a22_1 = reinterpret_cast<const ulonglong2*>(a_sm + 128);
        ull e00 = 0, e01 = 0, e10 = 0, e11 = 0;
#pragma unroll
        for (int q = 0; q < 32; q++) {
            ulonglong2 dv = d22[q];
            ulonglong2 av0 = a22_0[q];
            e00 = ffma2(av0.x, dv.x, e00);
            e01 = ffma2(av0.y, dv.y, e01);
            ulonglong2 av1 = a22_1[q];
            e10 = ffma2(av1.x, dv.x, e10);
            e11 = ffma2(av1.y, dv.y, e11);
        }
        float so0 = fmaxf(db + hsum2(e00, e01), 0.f);
        float so1 = fmaxf(db + hsum2(e10, e11), 0.f);
        so_p[0]   = so0;
        so_p[128] = so1;
        snxt[i]       = rh * so0 + scur[i] * rx;
        snxt[128 + i] = rh * so1 + scur[128 + i] * rx;
        __syncthreads();

        xs0 = nx0; xs1 = nx1;
        xs0p += G3; xs1p += G3;
        so_p += 24576;   // 3*64*128 per step
    }

    // CH even -> final state is in pp buffer 0
    g_SS[bid * 256 + i]       = s_sm[i];
    g_SS[bid * 256 + 128 + i] = s_sm[128 + i];
}

// ---------------- Phase C: h/c recurrence, chunked (64 CTAs x 384 threads) -----------
// f32x2 full 128-wide k (R9/R11-proven). Steps [t0, t0+CH); h/c state via g_HC.
__global__ __launch_bounds__(384, 1) void phaseC_kernel(
    const float* __restrict__ R,      // (128, 384)
    float* __restrict__ out,          // (B, T, U)
    int t0)
{
    __shared__ __align__(16) float h_sm[256];   // ping-pong [2][128]
    __shared__ float g_sm[384];

    const int b = blockIdx.x;
    const int j = threadIdx.x;

    ull wc[64];
#pragma unroll
    for (int q = 0; q < 64; q++) {
        float lo = __ldg(&R[(2 * q) * G3 + j]);
        float hi = __ldg(&R[(2 * q + 1) * G3 + j]);
        wc[q] = pack2(lo, hi);
    }

    float c = 0.f;
    if (j < 128) {
        if (t0 == 0) {
            h_sm[j] = 0.f;
        } else {
            h_sm[j] = g_HC[b * 256 + j];
            c       = g_HC[b * 256 + 128 + j];
        }
    }
    __syncthreads();

    const float* xk_ptr  = g_XK + (size_t)b * T_ * G3 + (size_t)t0 * G3 + j;
    const float* po_ptr  = g_PO + (size_t)t0 * 8192 + (size_t)b * U_ + j;   // valid only j<128
    float*       out_ptr = out  + (size_t)b * T_ * U_ + (size_t)t0 * U_ + j;

    float z0 = __ldg(xk_ptr);
    float og0 = (j < 128) ? __ldg(po_ptr) : 0.f;
    xk_ptr += G3; po_ptr += 8192;

#pragma unroll 1
    for (int t = 0; t < CH; t++) {
        float nz = 0.f, nog = 0.f;
        if (t + 1 < CH) {     // chunk-local guard: next chunk's PO not ready yet
            nz = __ldg(xk_ptr);
            if (j < 128) nog = __ldg(po_ptr);
        }

        const ulonglong2* h22 = reinterpret_cast<const ulonglong2*>(h_sm + (t & 1) * 128);
        ull acc0 = 0, acc1 = 0;
#pragma unroll
        for (int q = 0; q < 32; q++) {
            ulonglong2 hv = h22[q];
            acc0 = ffma2(hv.x, wc[2 * q],     acc0);
            acc1 = ffma2(hv.y, wc[2 * q + 1], acc1);
        }
        float z = z0 + hsum2(acc0, acc1);
        g_sm[j] = 1.f / (1.f + __expf(-z));
        __syncthreads();

        if (j < 128) {
            float ig = g_sm[j];
            float fg = g_sm[128 + j];
            float cg = g_sm[256 + j];
            c = fg * c + ig * tanhf(cg);
            float h = og0 * tanhf(c);
            *out_ptr = h;
            h_sm[((t & 1) ^ 1) * 128 + j] = h;
        }
        __syncthreads();

        z0 = nz; og0 = nog;
        xk_ptr += G3; po_ptr += 8192; out_ptr += U_;
    }

    // CH even -> final h in pp buffer 0
    if (j < 128) {
        g_HC[b * 256 + j]       = h_sm[j];
        g_HC[b * 256 + 128 + j] = c;
    }
}

// ---------------- launch ----------------
extern "C" void kernel_launch(void* const* d_in, const int* in_sizes, int n_in,
                              void* d_out, int out_size)
{
    (void)in_sizes; (void)n_in; (void)out_size;
    const float* x      = (const float*)d_in[0];   // (64,2048,128)
    const float* kern   = (const float*)d_in[1];   // (128,384)
    const float* reck   = (const float*)d_in[2];   // (128,384)
    const float* bias   = (const float*)d_in[3];   // (384)
    const float* skx    = (const float*)d_in[4];   // (3,128,128)
    const float* skh    = (const float*)d_in[5];   // (3,128,128)
    const float* tkan   = (const float*)d_in[6];   // (3,256)
    const float* dw     = (const float*)d_in[7];   // (3,128,128)
    const float* dbv    = (const float*)d_in[8];   // (3,128)
    const float* aggw   = (const float*)d_in[9];   // (384,128)
    const float* aggb   = (const float*)d_in[10];  // (128)
    float* out = (float*)d_out;

    void *pW2, *pXK, *pXS, *pSO, *pPO;
    cudaGetSymbolAddress(&pW2, g_W2);
    cudaGetSymbolAddress(&pXK, g_XK);
    cudaGetSymbolAddress(&pXS, g_XS);
    cudaGetSymbolAddress(&pSO, g_SO);
    cudaGetSymbolAddress(&pPO, g_PO);

    cudaFuncSetAttribute(phaseA_kernel, cudaFuncAttributeMaxDynamicSharedMemorySize,
                         SMEM_A2_FLOATS * (int)sizeof(float));

    static cudaStream_t s2 = nullptr, s3 = nullptr, s4 = nullptr;
    static cudaEvent_t evF = nullptr, evX = nullptr;
    static cudaEvent_t evA[NCH], evP[NCH], evC[NCH];
    if (s2 == nullptr) {
        cudaStreamCreateWithFlags(&s2, cudaStreamNonBlocking);
        cudaStreamCreateWithFlags(&s3, cudaStreamNonBlocking);
        cudaStreamCreateWithFlags(&s4, cudaStreamNonBlocking);
        cudaEventCreateWithFlags(&evF, cudaEventDisableTiming);
        cudaEventCreateWithFlags(&evX, cudaEventDisableTiming);
        for (int c = 0; c < NCH; c++) {
            cudaEventCreateWithFlags(&evA[c], cudaEventDisableTiming);
            cudaEventCreateWithFlags(&evP[c], cudaEventDisableTiming);
            cudaEventCreateWithFlags(&evC[c], cudaEventDisableTiming);
        }
    }

    // fork: XK = x@kernel + bias on side stream (independent of everything else)
    cudaEventRecord(evF, 0);
    cudaStreamWaitEvent(s2, evF, 0);
    {
        dim3 grid(BT / 128, G3 / 128);
        gemm128_kernel<<<grid, 256, 0, s2>>>(x, kern, bias, (float*)pXK, BT, D_, G3, 0);
    }
    cudaEventRecord(evX, s2);

    // main stream: W2 + DT transposes, XS GEMM
    build_w2_kernel<<<192, 256>>>(skx);
    build_dt_kernel<<<192, 256>>>(dw);
    {
        dim3 grid(BT / 128, G3 / 128);
        gemm128_kernel<<<grid, 256>>>(x, (const float*)pW2, nullptr, (float*)pXS, BT, D_, G3, 0);
    }

    // chunked pipeline: phaseA(c) -> PO(c) -> phaseC(c)
    for (int c = 0; c < NCH; c++) {
        const int t0 = c * CH;

        phaseA_kernel<<<96, 128, SMEM_A2_FLOATS * (int)sizeof(float)>>>(skh, dbv, tkan, t0);
        cudaEventRecord(evA[c], 0);

        cudaStreamWaitEvent(s3, evA[c], 0);
        {
            dim3 grid(CH * 64 / 128, 1);
            gemm128_kernel<<<grid, 256, 0, s3>>>(
                (const float*)pSO + (size_t)t0 * 64 * G3, aggw, aggb,
                (float*)pPO + (size_t)t0 * 64 * U_, CH * 64, G3, U_, 1);
        }
        cudaEventRecord(evP[c], s3);

        if (c == 0) cudaStreamWaitEvent(s4, evX, 0);
        cudaStreamWaitEvent(s4, evP[c], 0);
        phaseC_kernel<<<B_, G3, 0, s4>>>(reck, out, t0);
        cudaEventRecord(evC[c], s4);
    }

    // join
    cudaStreamWaitEvent(0, evC[NCH - 1], 0);
}